// round 1
// baseline (speedup 1.0000x reference)
#include <cuda_runtime.h>
#include <math.h>

// ---------------- scratch (device globals; no allocation allowed) ----------
#define TLEN 4096
__device__ float g_q[TLEN * 2048];    // [t][16][128]
__device__ float g_k[TLEN * 512];     // [t][4][128]
__device__ float g_v[TLEN * 512];     // [t][4][128]
__device__ float g_att[TLEN * 2048];  // [t][16][128]

// ---------------- SGEMM: C[M,N] = A[M,K] * B[N,K]^T (both K-major) --------
#define BM 128
#define BN 128
#define BK 16

__global__ __launch_bounds__(256) void sgemm_nt(
    const float* __restrict__ A, const float* __restrict__ B,
    float* __restrict__ C, int M, int N, int K)
{
    __shared__ float As[BK][BM];
    __shared__ float Bs[BK][BN];

    const int tid = threadIdx.x;
    const int m0 = blockIdx.y * BM;
    const int n0 = blockIdx.x * BN;
    const int tx = tid & 15;   // N direction (16)
    const int ty = tid >> 4;   // M direction (16)

    float acc[8][8];
#pragma unroll
    for (int i = 0; i < 8; i++)
#pragma unroll
        for (int j = 0; j < 8; j++) acc[i][j] = 0.0f;

    const int lrow = tid >> 2;        // 0..63
    const int lc4  = (tid & 3) * 4;   // 0,4,8,12

    for (int k0 = 0; k0 < K; k0 += BK) {
#pragma unroll
        for (int i = 0; i < 2; i++) {
            int row = lrow + i * 64;
            float4 a = *(const float4*)&A[(size_t)(m0 + row) * K + k0 + lc4];
            As[lc4 + 0][row] = a.x; As[lc4 + 1][row] = a.y;
            As[lc4 + 2][row] = a.z; As[lc4 + 3][row] = a.w;
            float4 b = *(const float4*)&B[(size_t)(n0 + row) * K + k0 + lc4];
            Bs[lc4 + 0][row] = b.x; Bs[lc4 + 1][row] = b.y;
            Bs[lc4 + 2][row] = b.z; Bs[lc4 + 3][row] = b.w;
        }
        __syncthreads();

#pragma unroll
        for (int kk = 0; kk < BK; kk++) {
            float av[8], bv[8];
            float4 a0 = *(const float4*)&As[kk][ty * 4];
            float4 a1 = *(const float4*)&As[kk][ty * 4 + 64];
            float4 b0 = *(const float4*)&Bs[kk][tx * 4];
            float4 b1 = *(const float4*)&Bs[kk][tx * 4 + 64];
            av[0] = a0.x; av[1] = a0.y; av[2] = a0.z; av[3] = a0.w;
            av[4] = a1.x; av[5] = a1.y; av[6] = a1.z; av[7] = a1.w;
            bv[0] = b0.x; bv[1] = b0.y; bv[2] = b0.z; bv[3] = b0.w;
            bv[4] = b1.x; bv[5] = b1.y; bv[6] = b1.z; bv[7] = b1.w;
#pragma unroll
            for (int i = 0; i < 8; i++)
#pragma unroll
                for (int j = 0; j < 8; j++)
                    acc[i][j] = fmaf(av[i], bv[j], acc[i][j]);
        }
        __syncthreads();
    }

#pragma unroll
    for (int i = 0; i < 8; i++) {
        int row = m0 + ty * 4 + (i & 3) + (i >> 2) * 64;
        float4 o0 = make_float4(acc[i][0], acc[i][1], acc[i][2], acc[i][3]);
        float4 o1 = make_float4(acc[i][4], acc[i][5], acc[i][6], acc[i][7]);
        *(float4*)&C[(size_t)row * N + n0 + tx * 4]      = o0;
        *(float4*)&C[(size_t)row * N + n0 + tx * 4 + 64] = o1;
    }
}

// ---------------- RoPE: apply to q (16 heads) and k (4 heads) -------------
__global__ __launch_bounds__(256) void rope_kernel(
    float* __restrict__ q, float* __restrict__ k)
{
    const int t = blockIdx.x;
    const int idx = blockIdx.y * 256 + threadIdx.x;   // 0..1279
    const int head = idx >> 6;                         // 0..19
    const int d = idx & 63;

    float invf = (float)pow(10000.0, -(double)d / 64.0);
    float fr = (float)t * invf;
    float c = cosf(fr), s = sinf(fr);

    float* base;
    if (head < 16) base = q + ((size_t)t * 16 + head) * 128;
    else           base = k + ((size_t)t * 4 + (head - 16)) * 128;

    float x1 = base[d];
    float x2 = base[d + 64];
    base[d]      = x1 * c - x2 * s;
    base[d + 64] = x1 * s + x2 * c;
}

// ---------------- windowed causal GQA attention ---------------------------
// block = 128 threads = 4 warps; warp w = kv head g; handles q heads 4g..4g+3
// keys s in [max(0, t-512), t]  (count <= 513)
#define WPAD 516

__global__ __launch_bounds__(128) void attn_kernel(
    const float* __restrict__ q, const float* __restrict__ k,
    const float* __restrict__ v, float* __restrict__ out)
{
    __shared__ float sc[4][4][WPAD];

    const int t = blockIdx.x;
    const int w = threadIdx.x >> 5;     // kv head g
    const int lane = threadIdx.x & 31;
    int s0 = t - 512; if (s0 < 0) s0 = 0;
    const int cnt = t - s0 + 1;
    const float scale = 0.08838834764831845f;  // 1/sqrt(128)

    // load the 4 grouped q vectors (this lane's 4 dims each)
    float4 qv[4];
#pragma unroll
    for (int r = 0; r < 4; r++)
        qv[r] = *(const float4*)&q[((size_t)t * 16 + w * 4 + r) * 128 + lane * 4];

    // ---- pass 1: scores --------------------------------------------------
    for (int j = 0; j < cnt; j++) {
        const int s = s0 + j;
        float4 kv = *(const float4*)&k[((size_t)s * 4 + w) * 128 + lane * 4];
        float d0 = qv[0].x * kv.x + qv[0].y * kv.y + qv[0].z * kv.z + qv[0].w * kv.w;
        float d1 = qv[1].x * kv.x + qv[1].y * kv.y + qv[1].z * kv.z + qv[1].w * kv.w;
        float d2 = qv[2].x * kv.x + qv[2].y * kv.y + qv[2].z * kv.z + qv[2].w * kv.w;
        float d3 = qv[3].x * kv.x + qv[3].y * kv.y + qv[3].z * kv.z + qv[3].w * kv.w;
#pragma unroll
        for (int off = 16; off; off >>= 1) {
            d0 += __shfl_xor_sync(0xffffffffu, d0, off);
            d1 += __shfl_xor_sync(0xffffffffu, d1, off);
            d2 += __shfl_xor_sync(0xffffffffu, d2, off);
            d3 += __shfl_xor_sync(0xffffffffu, d3, off);
        }
        if (lane == 0) {
            sc[w][0][j] = d0 * scale;
            sc[w][1][j] = d1 * scale;
            sc[w][2][j] = d2 * scale;
            sc[w][3][j] = d3 * scale;
        }
    }
    __syncwarp();

    // ---- softmax ---------------------------------------------------------
    float mx[4] = {-1e30f, -1e30f, -1e30f, -1e30f};
    for (int j = lane; j < cnt; j += 32) {
#pragma unroll
        for (int r = 0; r < 4; r++) mx[r] = fmaxf(mx[r], sc[w][r][j]);
    }
#pragma unroll
    for (int off = 16; off; off >>= 1) {
#pragma unroll
        for (int r = 0; r < 4; r++)
            mx[r] = fmaxf(mx[r], __shfl_xor_sync(0xffffffffu, mx[r], off));
    }
    float sum[4] = {0.f, 0.f, 0.f, 0.f};
    for (int j = lane; j < cnt; j += 32) {
#pragma unroll
        for (int r = 0; r < 4; r++) {
            float p = __expf(sc[w][r][j] - mx[r]);
            sc[w][r][j] = p;
            sum[r] += p;
        }
    }
#pragma unroll
    for (int off = 16; off; off >>= 1) {
#pragma unroll
        for (int r = 0; r < 4; r++)
            sum[r] += __shfl_xor_sync(0xffffffffu, sum[r], off);
    }
    float inv[4];
#pragma unroll
    for (int r = 0; r < 4; r++) inv[r] = 1.0f / sum[r];
    __syncwarp();

    // ---- pass 2: P @ V ---------------------------------------------------
    float4 acc[4];
#pragma unroll
    for (int r = 0; r < 4; r++) acc[r] = make_float4(0.f, 0.f, 0.f, 0.f);

    for (int j = 0; j < cnt; j++) {
        float4 vv = *(const float4*)&v[((size_t)(s0 + j) * 4 + w) * 128 + lane * 4];
#pragma unroll
        for (int r = 0; r < 4; r++) {
            float p = sc[w][r][j];
            acc[r].x = fmaf(p, vv.x, acc[r].x);
            acc[r].y = fmaf(p, vv.y, acc[r].y);
            acc[r].z = fmaf(p, vv.z, acc[r].z);
            acc[r].w = fmaf(p, vv.w, acc[r].w);
        }
    }

#pragma unroll
    for (int r = 0; r < 4; r++) {
        float4 o = make_float4(acc[r].x * inv[r], acc[r].y * inv[r],
                               acc[r].z * inv[r], acc[r].w * inv[r]);
        *(float4*)&out[((size_t)t * 16 + w * 4 + r) * 128 + lane * 4] = o;
    }
}

// ---------------- launcher -------------------------------------------------
extern "C" void kernel_launch(void* const* d_in, const int* in_sizes, int n_in,
                              void* d_out, int out_size)
{
    const float* x  = (const float*)d_in[0];
    const float* wq = (const float*)d_in[1];
    const float* wk = (const float*)d_in[2];
    const float* wv = (const float*)d_in[3];
    const float* wo = (const float*)d_in[4];
    float* out = (float*)d_out;

    float *q, *k, *v, *att;
    cudaGetSymbolAddress((void**)&q,   g_q);
    cudaGetSymbolAddress((void**)&k,   g_k);
    cudaGetSymbolAddress((void**)&v,   g_v);
    cudaGetSymbolAddress((void**)&att, g_att);

    // projections: C = A * W^T
    sgemm_nt<<<dim3(2048 / BN, TLEN / BM), 256>>>(x, wq, q, TLEN, 2048, 2048);
    sgemm_nt<<<dim3(512 / BN,  TLEN / BM), 256>>>(x, wk, k, TLEN, 512, 2048);
    sgemm_nt<<<dim3(512 / BN,  TLEN / BM), 256>>>(x, wv, v, TLEN, 512, 2048);

    rope_kernel<<<dim3(TLEN, 5), 256>>>(q, k);

    attn_kernel<<<TLEN, 128>>>(q, k, v, att);

    sgemm_nt<<<dim3(2048 / BN, TLEN / BM), 256>>>(att, wo, out, TLEN, 2048, 2048);
}

// round 3
// speedup vs baseline: 2.1637x; 2.1637x over previous
#include <cuda_runtime.h>
#include <math.h>
#include <stdint.h>

// ---------------- scratch (device globals; no allocation allowed) ----------
#define TLEN 4096
__device__ float g_q[TLEN * 2048];    // [t][16][128]
__device__ float g_k[TLEN * 512];     // [t][4][128]
__device__ float g_v[TLEN * 512];     // [t][4][128]
__device__ float g_att[TLEN * 2048];  // [t][16][128]

// ================= TF32 tensor-core GEMM: C[M,N] = A[M,K] * B[N,K]^T ======
// A row-major [M,K], B row-major [N,K] (== col-major K x N, exactly what
// mma .row.col wants). Block tile 128x128x32, 256 threads = 8 warps,
// warp tile 64x32 -> 4x4 mma(m16n8k8) tiles.
#define GPAD 36   // 32 k-floats padded to 36 -> bank = 4*gid + tig, conflict-free

__device__ __forceinline__ uint32_t f2tf(float x) {
    uint32_t r;
    asm("cvt.rna.tf32.f32 %0, %1;" : "=r"(r) : "f"(x));
    return r;
}

__device__ __forceinline__ void mma_tf32(float c[4], const uint32_t a[4],
                                         const uint32_t b[2]) {
    asm volatile(
        "mma.sync.aligned.m16n8k8.row.col.f32.tf32.tf32.f32 "
        "{%0,%1,%2,%3},{%4,%5,%6,%7},{%8,%9},{%0,%1,%2,%3};\n"
        : "+f"(c[0]), "+f"(c[1]), "+f"(c[2]), "+f"(c[3])
        : "r"(a[0]), "r"(a[1]), "r"(a[2]), "r"(a[3]), "r"(b[0]), "r"(b[1]));
}

__global__ __launch_bounds__(256, 2) void gemm_tf32(
    const float* __restrict__ A, const float* __restrict__ B,
    float* __restrict__ C, int M, int N, int K)
{
    __shared__ uint32_t As[128 * GPAD];
    __shared__ uint32_t Bs[128 * GPAD];

    const int tid  = threadIdx.x;
    const int warp = tid >> 5;
    const int lane = tid & 31;
    const int gid  = lane >> 2;   // 0..7
    const int tig  = lane & 3;    // 0..3
    const int wm   = (warp >> 2) * 64;  // warp M offset within tile (0 or 64)
    const int wn   = (warp & 3) * 32;   // warp N offset within tile
    const int m0   = blockIdx.y * 128;
    const int n0   = blockIdx.x * 128;

    // gmem load mapping: lanes 0..7 cover one row's 32 k-floats (coalesced 128B)
    const int lr = tid >> 3;         // 0..31 (rows, 4 iterations of +32)
    const int lk = (tid & 7) * 4;    // 0,4,...,28

    float acc[4][4][4];
#pragma unroll
    for (int mi = 0; mi < 4; mi++)
#pragma unroll
        for (int ni = 0; ni < 4; ni++)
#pragma unroll
            for (int r = 0; r < 4; r++) acc[mi][ni][r] = 0.0f;

    const float* Ap = A + (size_t)(m0 + lr) * K + lk;
    const float* Bp = B + (size_t)(n0 + lr) * K + lk;

    const int NT = K >> 5;   // K / 32
    float4 ra[4], rb[4];

    // prefetch tile 0
#pragma unroll
    for (int i = 0; i < 4; i++) {
        ra[i] = *(const float4*)(Ap + (size_t)i * 32 * K);
        rb[i] = *(const float4*)(Bp + (size_t)i * 32 * K);
    }

    for (int kt = 0; kt < NT; kt++) {
        // store prefetched tile to smem (with rna tf32 conversion)
#pragma unroll
        for (int i = 0; i < 4; i++) {
            uint32_t* as = &As[(lr + i * 32) * GPAD + lk];
            as[0] = f2tf(ra[i].x); as[1] = f2tf(ra[i].y);
            as[2] = f2tf(ra[i].z); as[3] = f2tf(ra[i].w);
            uint32_t* bs = &Bs[(lr + i * 32) * GPAD + lk];
            bs[0] = f2tf(rb[i].x); bs[1] = f2tf(rb[i].y);
            bs[2] = f2tf(rb[i].z); bs[3] = f2tf(rb[i].w);
        }
        __syncthreads();

        // prefetch next tile while computing this one
        if (kt + 1 < NT) {
            const float* Apn = Ap + (kt + 1) * 32;
            const float* Bpn = Bp + (kt + 1) * 32;
#pragma unroll
            for (int i = 0; i < 4; i++) {
                ra[i] = *(const float4*)(Apn + (size_t)i * 32 * K);
                rb[i] = *(const float4*)(Bpn + (size_t)i * 32 * K);
            }
        }

#pragma unroll
        for (int ks = 0; ks < 4; ks++) {
            const int kk = ks * 8;
            uint32_t af[4][4];
#pragma unroll
            for (int mi = 0; mi < 4; mi++) {
                const int r0 = wm + mi * 16 + gid;
                af[mi][0] = As[(r0    ) * GPAD + kk + tig];
                af[mi][1] = As[(r0 + 8) * GPAD + kk + tig];
                af[mi][2] = As[(r0    ) * GPAD + kk + tig + 4];
                af[mi][3] = As[(r0 + 8) * GPAD + kk + tig + 4];
            }
            uint32_t bf[4][2];
#pragma unroll
            for (int ni = 0; ni < 4; ni++) {
                const int c0 = wn + ni * 8 + gid;
                bf[ni][0] = Bs[c0 * GPAD + kk + tig];
                bf[ni][1] = Bs[c0 * GPAD + kk + tig + 4];
            }
#pragma unroll
            for (int mi = 0; mi < 4; mi++)
#pragma unroll
                for (int ni = 0; ni < 4; ni++)
                    mma_tf32(acc[mi][ni], af[mi], bf[ni]);
        }
        __syncthreads();
    }

    // epilogue: c0,c1 -> (row, 2*tig..2*tig+1), c2,c3 -> row+8
#pragma unroll
    for (int mi = 0; mi < 4; mi++) {
        const int r0 = m0 + wm + mi * 16 + gid;
#pragma unroll
        for (int ni = 0; ni < 4; ni++) {
            const int c = n0 + wn + ni * 8 + tig * 2;
            *(float2*)&C[(size_t)r0 * N + c] =
                make_float2(acc[mi][ni][0], acc[mi][ni][1]);
            *(float2*)&C[(size_t)(r0 + 8) * N + c] =
                make_float2(acc[mi][ni][2], acc[mi][ni][3]);
        }
    }
}

// ---------------- RoPE: apply to q (16 heads) and k (4 heads) -------------
__global__ __launch_bounds__(256) void rope_kernel(
    float* __restrict__ q, float* __restrict__ k)
{
    const int t = blockIdx.x;
    const int idx = blockIdx.y * 256 + threadIdx.x;   // 0..1279
    const int head = idx >> 6;                         // 0..19
    const int d = idx & 63;

    // 1/10000^(d/64) = 2^(-d * log2(10000)/64)
    const float invf = exp2f((float)d * (-13.287712379549449f / 64.0f));
    float fr = (float)t * invf;
    float c = cosf(fr), s = sinf(fr);

    float* base;
    if (head < 16) base = q + ((size_t)t * 16 + head) * 128;
    else           base = k + ((size_t)t * 4 + (head - 16)) * 128;

    float x1 = base[d];
    float x2 = base[d + 64];
    base[d]      = x1 * c - x2 * s;
    base[d + 64] = x1 * s + x2 * c;
}

// ---------------- windowed causal GQA attention ---------------------------
// block = 128 threads = 4 warps; warp w = kv head g; handles q heads 4g..4g+3
#define WPAD 516

__global__ __launch_bounds__(128) void attn_kernel(
    const float* __restrict__ q, const float* __restrict__ k,
    const float* __restrict__ v, float* __restrict__ out)
{
    __shared__ float sc[4][4][WPAD];

    const int t = blockIdx.x;
    const int w = threadIdx.x >> 5;     // kv head g
    const int lane = threadIdx.x & 31;
    int s0 = t - 512; if (s0 < 0) s0 = 0;
    const int cnt = t - s0 + 1;
    const float scale = 0.08838834764831845f;  // 1/sqrt(128)

    float4 qv[4];
#pragma unroll
    for (int r = 0; r < 4; r++)
        qv[r] = *(const float4*)&q[((size_t)t * 16 + w * 4 + r) * 128 + lane * 4];

    for (int j = 0; j < cnt; j++) {
        const int s = s0 + j;
        float4 kv = *(const float4*)&k[((size_t)s * 4 + w) * 128 + lane * 4];
        float d0 = qv[0].x * kv.x + qv[0].y * kv.y + qv[0].z * kv.z + qv[0].w * kv.w;
        float d1 = qv[1].x * kv.x + qv[1].y * kv.y + qv[1].z * kv.z + qv[1].w * kv.w;
        float d2 = qv[2].x * kv.x + qv[2].y * kv.y + qv[2].z * kv.z + qv[2].w * kv.w;
        float d3 = qv[3].x * kv.x + qv[3].y * kv.y + qv[3].z * kv.z + qv[3].w * kv.w;
#pragma unroll
        for (int off = 16; off; off >>= 1) {
            d0 += __shfl_xor_sync(0xffffffffu, d0, off);
            d1 += __shfl_xor_sync(0xffffffffu, d1, off);
            d2 += __shfl_xor_sync(0xffffffffu, d2, off);
            d3 += __shfl_xor_sync(0xffffffffu, d3, off);
        }
        if (lane == 0) {
            sc[w][0][j] = d0 * scale;
            sc[w][1][j] = d1 * scale;
            sc[w][2][j] = d2 * scale;
            sc[w][3][j] = d3 * scale;
        }
    }
    __syncwarp();

    float mx[4] = {-1e30f, -1e30f, -1e30f, -1e30f};
    for (int j = lane; j < cnt; j += 32) {
#pragma unroll
        for (int r = 0; r < 4; r++) mx[r] = fmaxf(mx[r], sc[w][r][j]);
    }
#pragma unroll
    for (int off = 16; off; off >>= 1) {
#pragma unroll
        for (int r = 0; r < 4; r++)
            mx[r] = fmaxf(mx[r], __shfl_xor_sync(0xffffffffu, mx[r], off));
    }
    float sum[4] = {0.f, 0.f, 0.f, 0.f};
    for (int j = lane; j < cnt; j += 32) {
#pragma unroll
        for (int r = 0; r < 4; r++) {
            float p = __expf(sc[w][r][j] - mx[r]);
            sc[w][r][j] = p;
            sum[r] += p;
        }
    }
#pragma unroll
    for (int off = 16; off; off >>= 1) {
#pragma unroll
        for (int r = 0; r < 4; r++)
            sum[r] += __shfl_xor_sync(0xffffffffu, sum[r], off);
    }
    float inv[4];
#pragma unroll
    for (int r = 0; r < 4; r++) inv[r] = 1.0f / sum[r];
    __syncwarp();

    float4 acc[4];
#pragma unroll
    for (int r = 0; r < 4; r++) acc[r] = make_float4(0.f, 0.f, 0.f, 0.f);

    for (int j = 0; j < cnt; j++) {
        float4 vv = *(const float4*)&v[((size_t)(s0 + j) * 4 + w) * 128 + lane * 4];
#pragma unroll
        for (int r = 0; r < 4; r++) {
            float p = sc[w][r][j];
            acc[r].x = fmaf(p, vv.x, acc[r].x);
            acc[r].y = fmaf(p, vv.y, acc[r].y);
            acc[r].z = fmaf(p, vv.z, acc[r].z);
            acc[r].w = fmaf(p, vv.w, acc[r].w);
        }
    }

#pragma unroll
    for (int r = 0; r < 4; r++) {
        float4 o = make_float4(acc[r].x * inv[r], acc[r].y * inv[r],
                               acc[r].z * inv[r], acc[r].w * inv[r]);
        *(float4*)&out[((size_t)t * 16 + w * 4 + r) * 128 + lane * 4] = o;
    }
}

// ---------------- launcher -------------------------------------------------
extern "C" void kernel_launch(void* const* d_in, const int* in_sizes, int n_in,
                              void* d_out, int out_size)
{
    const float* x  = (const float*)d_in[0];
    const float* wq = (const float*)d_in[1];
    const float* wk = (const float*)d_in[2];
    const float* wv = (const float*)d_in[3];
    const float* wo = (const float*)d_in[4];
    float* out = (float*)d_out;

    float *q, *k, *v, *att;
    cudaGetSymbolAddress((void**)&q,   g_q);
    cudaGetSymbolAddress((void**)&k,   g_k);
    cudaGetSymbolAddress((void**)&v,   g_v);
    cudaGetSymbolAddress((void**)&att, g_att);

    // projections: C = A * W^T  (tf32 tensor cores)
    gemm_tf32<<<dim3(2048 / 128, TLEN / 128), 256>>>(x, wq, q, TLEN, 2048, 2048);
    gemm_tf32<<<dim3(512 / 128,  TLEN / 128), 256>>>(x, wk, k, TLEN, 512, 2048);
    gemm_tf32<<<dim3(512 / 128,  TLEN / 128), 256>>>(x, wv, v, TLEN, 512, 2048);

    rope_kernel<<<dim3(TLEN, 5), 256>>>(q, k);

    attn_kernel<<<TLEN, 128>>>(q, k, v, att);

    gemm_tf32<<<dim3(2048 / 128, TLEN / 128), 256>>>(att, wo, out, TLEN, 2048, 2048);
}

// round 6
// speedup vs baseline: 4.2391x; 1.9592x over previous
#include <cuda_runtime.h>
#include <math.h>
#include <stdint.h>

// ---------------- scratch (device globals; no allocation allowed) ----------
#define TLEN 4096
__device__ float g_q[TLEN * 2048];    // [t][16][128]
__device__ float g_k[TLEN * 512];     // [t][4][128]
__device__ float g_v[TLEN * 512];     // [t][4][128]
__device__ float g_att[TLEN * 2048];  // [t][16][128]

__device__ __forceinline__ uint32_t f2tf(float x) {
    uint32_t r;
    asm("cvt.rna.tf32.f32 %0, %1;" : "=r"(r) : "f"(x));
    return r;
}

__device__ __forceinline__ void mma_tf32(float c[4], const uint32_t a[4],
                                         const uint32_t b0, const uint32_t b1) {
    asm volatile(
        "mma.sync.aligned.m16n8k8.row.col.f32.tf32.tf32.f32 "
        "{%0,%1,%2,%3},{%4,%5,%6,%7},{%8,%9},{%0,%1,%2,%3};\n"
        : "+f"(c[0]), "+f"(c[1]), "+f"(c[2]), "+f"(c[3])
        : "r"(a[0]), "r"(a[1]), "r"(a[2]), "r"(a[3]), "r"(b0), "r"(b1));
}

// ================= TF32 tensor-core GEMM: C[M,N] = A[M,K] * B[N,K]^T ======
#define GPAD 36

__global__ __launch_bounds__(256, 2) void gemm_tf32(
    const float* __restrict__ A, const float* __restrict__ B,
    float* __restrict__ C, int M, int N, int K)
{
    __shared__ uint32_t As[128 * GPAD];
    __shared__ uint32_t Bs[128 * GPAD];

    const int tid  = threadIdx.x;
    const int warp = tid >> 5;
    const int lane = tid & 31;
    const int gid  = lane >> 2;
    const int tig  = lane & 3;
    const int wm   = (warp >> 2) * 64;
    const int wn   = (warp & 3) * 32;
    const int m0   = blockIdx.y * 128;
    const int n0   = blockIdx.x * 128;

    const int lr = tid >> 3;
    const int lk = (tid & 7) * 4;

    float acc[4][4][4];
#pragma unroll
    for (int mi = 0; mi < 4; mi++)
#pragma unroll
        for (int ni = 0; ni < 4; ni++)
#pragma unroll
            for (int r = 0; r < 4; r++) acc[mi][ni][r] = 0.0f;

    const float* Ap = A + (size_t)(m0 + lr) * K + lk;
    const float* Bp = B + (size_t)(n0 + lr) * K + lk;

    const int NT = K >> 5;
    float4 ra[4], rb[4];

#pragma unroll
    for (int i = 0; i < 4; i++) {
        ra[i] = *(const float4*)(Ap + (size_t)i * 32 * K);
        rb[i] = *(const float4*)(Bp + (size_t)i * 32 * K);
    }

    for (int kt = 0; kt < NT; kt++) {
#pragma unroll
        for (int i = 0; i < 4; i++) {
            uint32_t* as = &As[(lr + i * 32) * GPAD + lk];
            as[0] = f2tf(ra[i].x); as[1] = f2tf(ra[i].y);
            as[2] = f2tf(ra[i].z); as[3] = f2tf(ra[i].w);
            uint32_t* bs = &Bs[(lr + i * 32) * GPAD + lk];
            bs[0] = f2tf(rb[i].x); bs[1] = f2tf(rb[i].y);
            bs[2] = f2tf(rb[i].z); bs[3] = f2tf(rb[i].w);
        }
        __syncthreads();

        if (kt + 1 < NT) {
            const float* Apn = Ap + (kt + 1) * 32;
            const float* Bpn = Bp + (kt + 1) * 32;
#pragma unroll
            for (int i = 0; i < 4; i++) {
                ra[i] = *(const float4*)(Apn + (size_t)i * 32 * K);
                rb[i] = *(const float4*)(Bpn + (size_t)i * 32 * K);
            }
        }

#pragma unroll
        for (int ks = 0; ks < 4; ks++) {
            const int kk = ks * 8;
            uint32_t af[4][4];
#pragma unroll
            for (int mi = 0; mi < 4; mi++) {
                const int r0 = wm + mi * 16 + gid;
                af[mi][0] = As[(r0    ) * GPAD + kk + tig];
                af[mi][1] = As[(r0 + 8) * GPAD + kk + tig];
                af[mi][2] = As[(r0    ) * GPAD + kk + tig + 4];
                af[mi][3] = As[(r0 + 8) * GPAD + kk + tig + 4];
            }
            uint32_t bf[4][2];
#pragma unroll
            for (int ni = 0; ni < 4; ni++) {
                const int c0 = wn + ni * 8 + gid;
                bf[ni][0] = Bs[c0 * GPAD + kk + tig];
                bf[ni][1] = Bs[c0 * GPAD + kk + tig + 4];
            }
#pragma unroll
            for (int mi = 0; mi < 4; mi++)
#pragma unroll
                for (int ni = 0; ni < 4; ni++)
                    mma_tf32(acc[mi][ni], af[mi], bf[ni][0], bf[ni][1]);
        }
        __syncthreads();
    }

#pragma unroll
    for (int mi = 0; mi < 4; mi++) {
        const int r0 = m0 + wm + mi * 16 + gid;
#pragma unroll
        for (int ni = 0; ni < 4; ni++) {
            const int c = n0 + wn + ni * 8 + tig * 2;
            *(float2*)&C[(size_t)r0 * N + c] =
                make_float2(acc[mi][ni][0], acc[mi][ni][1]);
            *(float2*)&C[(size_t)(r0 + 8) * N + c] =
                make_float2(acc[mi][ni][2], acc[mi][ni][3]);
        }
    }
}

// ---------------- RoPE ----------------------------------------------------
__global__ __launch_bounds__(256) void rope_kernel(
    float* __restrict__ q, float* __restrict__ k)
{
    const int t = blockIdx.x;
    const int idx = blockIdx.y * 256 + threadIdx.x;
    const int head = idx >> 6;
    const int d = idx & 63;

    const float invf = exp2f((float)d * (-13.287712379549449f / 64.0f));
    float fr = (float)t * invf;
    float c = cosf(fr), s = sinf(fr);

    float* base;
    if (head < 16) base = q + ((size_t)t * 16 + head) * 128;
    else           base = k + ((size_t)t * 4 + (head - 16)) * 128;

    float x1 = base[d];
    float x2 = base[d + 64];
    base[d]      = x1 * c - x2 * s;
    base[d + 64] = x1 * s + x2 * c;
}

// =============== tensor-core flash attention ==============================
// grid (T/32, KV_HEADS). 256 threads = 8 warps. M tile = 32 timesteps x 4
// grouped q-heads = 128 rows; warp w owns rows [16w,16w+16). 17 key chunks
// of 32. K chunk in SMEM [32][132]; after QK the same buffer holds the
// per-warp P tiles [8][16][36]. V kept row-major [key][132].
#define KSTR 132
#define PSTR 36

__global__ __launch_bounds__(256) void attn_mma(
    const float* __restrict__ q, const float* __restrict__ k,
    const float* __restrict__ v, float* __restrict__ out)
{
    __shared__ uint32_t KP[4608];          // max(32*132, 8*16*36)
    __shared__ uint32_t Vs[32 * KSTR];

    const int t0   = blockIdx.x * 32;
    const int gh   = blockIdx.y;
    const int tid  = threadIdx.x;
    const int warp = tid >> 5;
    const int lane = tid & 31;
    const int g    = lane >> 2;
    const int tig  = lane & 3;
    const float scale = 0.08838834764831845f;

    const int mA = warp * 16 + g;
    const int mB = mA + 8;
    const int tA = t0 + (mA & 31), tB = t0 + (mB & 31);
    const int hA = gh * 4 + (mA >> 5), hB = gh * 4 + (mB >> 5);

    // Q fragments (one-time gmem read)
    uint32_t qa[16][4];
    const float* qAp = q + ((size_t)tA * 16 + hA) * 128;
    const float* qBp = q + ((size_t)tB * 16 + hB) * 128;
#pragma unroll
    for (int ks = 0; ks < 16; ks++) {
        qa[ks][0] = f2tf(qAp[8 * ks + tig]);
        qa[ks][1] = f2tf(qBp[8 * ks + tig]);
        qa[ks][2] = f2tf(qAp[8 * ks + tig + 4]);
        qa[ks][3] = f2tf(qBp[8 * ks + tig + 4]);
    }

    float oa[16][4];
#pragma unroll
    for (int i = 0; i < 16; i++)
#pragma unroll
        for (int r = 0; r < 4; r++) oa[i][r] = 0.0f;
    float rmA = -1e30f, rmB = -1e30f, rlA = 0.0f, rlB = 0.0f;

    uint32_t* Pw = &KP[warp * 16 * PSTR];

    for (int c = 0; c < 17; c++) {
        const int sb = t0 - 512 + 32 * c;
        if (sb + 31 < 0) continue;

        // load K and V chunks (vectorized, tf32-converted)
#pragma unroll
        for (int i = 0; i < 4; i++) {
            int idx = tid + 256 * i;
            int row = idx >> 5;
            int c4  = (idx & 31) * 4;
            int s = sb + row;
            float4 k4 = make_float4(0.f, 0.f, 0.f, 0.f);
            float4 v4 = make_float4(0.f, 0.f, 0.f, 0.f);
            if (s >= 0) {
                k4 = *(const float4*)&k[((size_t)s * 4 + gh) * 128 + c4];
                v4 = *(const float4*)&v[((size_t)s * 4 + gh) * 128 + c4];
            }
            uint4 kp = make_uint4(f2tf(k4.x), f2tf(k4.y), f2tf(k4.z), f2tf(k4.w));
            uint4 vp = make_uint4(f2tf(v4.x), f2tf(v4.y), f2tf(v4.z), f2tf(v4.w));
            *(uint4*)&KP[row * KSTR + c4] = kp;
            *(uint4*)&Vs[row * KSTR + c4] = vp;
        }
        __syncthreads();

        // S = Q K^T (16x32 per warp)
        float sf[4][4];
#pragma unroll
        for (int ni = 0; ni < 4; ni++)
#pragma unroll
            for (int r = 0; r < 4; r++) sf[ni][r] = 0.0f;
#pragma unroll
        for (int ks = 0; ks < 16; ks++) {
            const int kk = ks * 8;
#pragma unroll
            for (int ni = 0; ni < 4; ni++) {
                uint32_t b0 = KP[(ni * 8 + g) * KSTR + kk + tig];
                uint32_t b1 = KP[(ni * 8 + g) * KSTR + kk + tig + 4];
                mma_tf32(sf[ni], qa[ks], b0, b1);
            }
        }
        __syncthreads();   // everyone done reading KP before P overwrites it

        // mask + chunk max
        float cmA = -1e30f, cmB = -1e30f;
#pragma unroll
        for (int ni = 0; ni < 4; ni++) {
#pragma unroll
            for (int jj = 0; jj < 2; jj++) {
                const int s = sb + ni * 8 + tig * 2 + jj;
                bool okA = (s >= 0) && (s <= tA) && (tA - s <= 512);
                bool okB = (s >= 0) && (s <= tB) && (tB - s <= 512);
                sf[ni][jj]     = okA ? sf[ni][jj]     * scale : -1e30f;
                sf[ni][2 + jj] = okB ? sf[ni][2 + jj] * scale : -1e30f;
                cmA = fmaxf(cmA, sf[ni][jj]);
                cmB = fmaxf(cmB, sf[ni][2 + jj]);
            }
        }
        cmA = fmaxf(cmA, __shfl_xor_sync(0xffffffffu, cmA, 1));
        cmA = fmaxf(cmA, __shfl_xor_sync(0xffffffffu, cmA, 2));
        cmB = fmaxf(cmB, __shfl_xor_sync(0xffffffffu, cmB, 1));
        cmB = fmaxf(cmB, __shfl_xor_sync(0xffffffffu, cmB, 2));

        const float nmA = fmaxf(rmA, cmA), nmB = fmaxf(rmB, cmB);
        const float alA = __expf(rmA - nmA), alB = __expf(rmB - nmB);
        rmA = nmA; rmB = nmB;

        float clA = 0.f, clB = 0.f;
#pragma unroll
        for (int ni = 0; ni < 4; ni++) {
            float p0 = __expf(sf[ni][0] - nmA);
            float p1 = __expf(sf[ni][1] - nmA);
            float p2 = __expf(sf[ni][2] - nmB);
            float p3 = __expf(sf[ni][3] - nmB);
            clA += p0 + p1; clB += p2 + p3;
            const int col = ni * 8 + tig * 2;
            Pw[g * PSTR + col]           = f2tf(p0);
            Pw[g * PSTR + col + 1]       = f2tf(p1);
            Pw[(g + 8) * PSTR + col]     = f2tf(p2);
            Pw[(g + 8) * PSTR + col + 1] = f2tf(p3);
        }
        clA += __shfl_xor_sync(0xffffffffu, clA, 1);
        clA += __shfl_xor_sync(0xffffffffu, clA, 2);
        clB += __shfl_xor_sync(0xffffffffu, clB, 1);
        clB += __shfl_xor_sync(0xffffffffu, clB, 2);
        rlA = rlA * alA + clA;
        rlB = rlB * alB + clB;

#pragma unroll
        for (int ni2 = 0; ni2 < 16; ni2++) {
            oa[ni2][0] *= alA; oa[ni2][1] *= alA;
            oa[ni2][2] *= alB; oa[ni2][3] *= alB;
        }
        __syncwarp();

        // O += P V
#pragma unroll
        for (int ks = 0; ks < 4; ks++) {
            const int kk = ks * 8;
            uint32_t pa[4];
            pa[0] = Pw[g * PSTR + kk + tig];
            pa[1] = Pw[(g + 8) * PSTR + kk + tig];
            pa[2] = Pw[g * PSTR + kk + tig + 4];
            pa[3] = Pw[(g + 8) * PSTR + kk + tig + 4];
#pragma unroll
            for (int ni2 = 0; ni2 < 16; ni2++) {
                uint32_t b0 = Vs[(kk + tig) * KSTR + ni2 * 8 + g];
                uint32_t b1 = Vs[(kk + tig + 4) * KSTR + ni2 * 8 + g];
                mma_tf32(oa[ni2], pa, b0, b1);
            }
        }
        __syncthreads();   // before next chunk overwrites KP / Vs
    }

    const float ilA = 1.0f / rlA, ilB = 1.0f / rlB;
    float* oAp = out + ((size_t)tA * 16 + hA) * 128;
    float* oBp = out + ((size_t)tB * 16 + hB) * 128;
#pragma unroll
    for (int ni2 = 0; ni2 < 16; ni2++) {
        const int d0 = ni2 * 8 + tig * 2;
        *(float2*)&oAp[d0] = make_float2(oa[ni2][0] * ilA, oa[ni2][1] * ilA);
        *(float2*)&oBp[d0] = make_float2(oa[ni2][2] * ilB, oa[ni2][3] * ilB);
    }
}

// ---------------- launcher -------------------------------------------------
extern "C" void kernel_launch(void* const* d_in, const int* in_sizes, int n_in,
                              void* d_out, int out_size)
{
    const float* x  = (const float*)d_in[0];
    const float* wq = (const float*)d_in[1];
    const float* wk = (const float*)d_in[2];
    const float* wv = (const float*)d_in[3];
    const float* wo = (const float*)d_in[4];
    float* out = (float*)d_out;

    float *q, *k, *v, *att;
    cudaGetSymbolAddress((void**)&q,   g_q);
    cudaGetSymbolAddress((void**)&k,   g_k);
    cudaGetSymbolAddress((void**)&v,   g_v);
    cudaGetSymbolAddress((void**)&att, g_att);

    gemm_tf32<<<dim3(2048 / 128, TLEN / 128), 256>>>(x, wq, q, TLEN, 2048, 2048);
    gemm_tf32<<<dim3(512 / 128,  TLEN / 128), 256>>>(x, wk, k, TLEN, 512, 2048);
    gemm_tf32<<<dim3(512 / 128,  TLEN / 128), 256>>>(x, wv, v, TLEN, 512, 2048);

    rope_kernel<<<dim3(TLEN, 5), 256>>>(q, k);

    attn_mma<<<dim3(TLEN / 32, 4), 256>>>(q, k, v, att);

    gemm_tf32<<<dim3(2048 / 128, TLEN / 128), 256>>>(att, wo, out, TLEN, 2048, 2048);
}

// round 9
// speedup vs baseline: 4.6419x; 1.0950x over previous
#include <cuda_runtime.h>
#include <math.h>
#include <stdint.h>

// ---------------- scratch (device globals; no allocation allowed) ----------
#define TLEN 4096
__device__ float g_q[TLEN * 2048];
__device__ float g_k[TLEN * 512];
__device__ float g_v[TLEN * 512];
__device__ float g_att[TLEN * 2048];
__device__ float g_wcat[3072 * 2048];   // [wq;wk;wv] concatenated

__device__ __forceinline__ uint32_t f2tf(float x) {
    uint32_t r;
    asm("cvt.rna.tf32.f32 %0, %1;" : "=r"(r) : "f"(x));
    return r;
}
__device__ __forceinline__ void mma_tf32(float c[4], const uint32_t a[4],
                                         const uint32_t b0, const uint32_t b1) {
    asm volatile(
        "mma.sync.aligned.m16n8k8.row.col.f32.tf32.tf32.f32 "
        "{%0,%1,%2,%3},{%4,%5,%6,%7},{%8,%9},{%0,%1,%2,%3};\n"
        : "+f"(c[0]), "+f"(c[1]), "+f"(c[2]), "+f"(c[3])
        : "r"(a[0]), "r"(a[1]), "r"(a[2]), "r"(a[3]), "r"(b0), "r"(b1));
}

// ====== double-buffered TF32 GEMM: C[M,N] = A[M,K] * B[N,K]^T =============
// Tile 128x128x32, 256 thr = 8 warps, warp tile 64x32 (4x4 m16n8k8).
// Dynamic smem: 2 stages x (As[128][36] + Bs[128][36]); 1 sync per K-tile.
// Output routed per-CTA across up to 3 column regions (for fused QKV).
#define GPAD 36
#define STGW 9216          // uint32 words per stage (2 * 128 * 36)
#define GEMM_SMEM 73728    // bytes

__global__ __launch_bounds__(256, 2) void gemm_db(
    const float* __restrict__ A, const float* __restrict__ B,
    float* __restrict__ c0, int nc0, int ld0,
    float* __restrict__ c1, int nc1, int ld1,
    float* __restrict__ c2, int ld2, int K)
{
    extern __shared__ uint32_t sm[];

    const int tid  = threadIdx.x;
    const int warp = tid >> 5;
    const int lane = tid & 31;
    const int gid  = lane >> 2;
    const int tig  = lane & 3;
    const int wm   = (warp >> 2) * 64;
    const int wn   = (warp & 3) * 32;
    const int m0   = blockIdx.y * 128;
    const int n0   = blockIdx.x * 128;

    const int lr = tid >> 3;         // 0..31
    const int lk = (tid & 7) * 4;    // 0..28

    float acc[4][4][4];
#pragma unroll
    for (int mi = 0; mi < 4; mi++)
#pragma unroll
        for (int ni = 0; ni < 4; ni++)
#pragma unroll
            for (int r = 0; r < 4; r++) acc[mi][ni][r] = 0.0f;

    const float* Ap = A + (size_t)(m0 + lr) * K + lk;
    const float* Bp = B + (size_t)(n0 + lr) * K + lk;
    const int NT = K >> 5;

    // prologue: tile 0 -> stage 0
    {
        float4 ra[4], rb[4];
#pragma unroll
        for (int i = 0; i < 4; i++) {
            ra[i] = *(const float4*)(Ap + (size_t)i * 32 * K);
            rb[i] = *(const float4*)(Bp + (size_t)i * 32 * K);
        }
        uint32_t* As = sm;
        uint32_t* Bs = sm + 4608;
#pragma unroll
        for (int i = 0; i < 4; i++) {
            uint32_t* as = &As[(lr + i * 32) * GPAD + lk];
            as[0] = f2tf(ra[i].x); as[1] = f2tf(ra[i].y);
            as[2] = f2tf(ra[i].z); as[3] = f2tf(ra[i].w);
            uint32_t* bs = &Bs[(lr + i * 32) * GPAD + lk];
            bs[0] = f2tf(rb[i].x); bs[1] = f2tf(rb[i].y);
            bs[2] = f2tf(rb[i].z); bs[3] = f2tf(rb[i].w);
        }
    }
    __syncthreads();

    for (int kt = 0; kt < NT; kt++) {
        uint32_t* As = sm + (kt & 1) * STGW;
        uint32_t* Bs = As + 4608;
        uint32_t* Asn = sm + ((kt + 1) & 1) * STGW;
        uint32_t* Bsn = Asn + 4608;
        const bool more = (kt + 1 < NT);

        float4 ra[4];
        if (more) {
            const float* Apn = Ap + (kt + 1) * 32;
#pragma unroll
            for (int i = 0; i < 4; i++)
                ra[i] = *(const float4*)(Apn + (size_t)i * 32 * K);
        }

        // ks 0,1
#pragma unroll
        for (int ks = 0; ks < 2; ks++) {
            const int kk = ks * 8;
            uint32_t af[4][4];
#pragma unroll
            for (int mi = 0; mi < 4; mi++) {
                const int r0 = wm + mi * 16 + gid;
                af[mi][0] = As[(r0    ) * GPAD + kk + tig];
                af[mi][1] = As[(r0 + 8) * GPAD + kk + tig];
                af[mi][2] = As[(r0    ) * GPAD + kk + tig + 4];
                af[mi][3] = As[(r0 + 8) * GPAD + kk + tig + 4];
            }
#pragma unroll
            for (int ni = 0; ni < 4; ni++) {
                const int c0i = wn + ni * 8 + gid;
                uint32_t b0 = Bs[c0i * GPAD + kk + tig];
                uint32_t b1 = Bs[c0i * GPAD + kk + tig + 4];
#pragma unroll
                for (int mi = 0; mi < 4; mi++)
                    mma_tf32(acc[mi][ni], af[mi], b0, b1);
            }
        }

        float4 rb[4];
        if (more) {
#pragma unroll
            for (int i = 0; i < 4; i++) {
                uint32_t* as = &Asn[(lr + i * 32) * GPAD + lk];
                as[0] = f2tf(ra[i].x); as[1] = f2tf(ra[i].y);
                as[2] = f2tf(ra[i].z); as[3] = f2tf(ra[i].w);
            }
            const float* Bpn = Bp + (kt + 1) * 32;
#pragma unroll
            for (int i = 0; i < 4; i++)
                rb[i] = *(const float4*)(Bpn + (size_t)i * 32 * K);
        }

        // ks 2,3
#pragma unroll
        for (int ks = 2; ks < 4; ks++) {
            const int kk = ks * 8;
            uint32_t af[4][4];
#pragma unroll
            for (int mi = 0; mi < 4; mi++) {
                const int r0 = wm + mi * 16 + gid;
                af[mi][0] = As[(r0    ) * GPAD + kk + tig];
                af[mi][1] = As[(r0 + 8) * GPAD + kk + tig];
                af[mi][2] = As[(r0    ) * GPAD + kk + tig + 4];
                af[mi][3] = As[(r0 + 8) * GPAD + kk + tig + 4];
            }
#pragma unroll
            for (int ni = 0; ni < 4; ni++) {
                const int c0i = wn + ni * 8 + gid;
                uint32_t b0 = Bs[c0i * GPAD + kk + tig];
                uint32_t b1 = Bs[c0i * GPAD + kk + tig + 4];
#pragma unroll
                for (int mi = 0; mi < 4; mi++)
                    mma_tf32(acc[mi][ni], af[mi], b0, b1);
            }
        }

        if (more) {
#pragma unroll
            for (int i = 0; i < 4; i++) {
                uint32_t* bs = &Bsn[(lr + i * 32) * GPAD + lk];
                bs[0] = f2tf(rb[i].x); bs[1] = f2tf(rb[i].y);
                bs[2] = f2tf(rb[i].z); bs[3] = f2tf(rb[i].w);
            }
        }
        __syncthreads();
    }

    // CTA-level output routing (region boundaries are 128-aligned)
    float* dst; int coff, ld;
    if (n0 < nc0)            { dst = c0; coff = n0;             ld = ld0; }
    else if (n0 < nc0 + nc1) { dst = c1; coff = n0 - nc0;       ld = ld1; }
    else                     { dst = c2; coff = n0 - nc0 - nc1; ld = ld2; }

#pragma unroll
    for (int mi = 0; mi < 4; mi++) {
        const int r0 = m0 + wm + mi * 16 + gid;
#pragma unroll
        for (int ni = 0; ni < 4; ni++) {
            const int c = coff + wn + ni * 8 + tig * 2;
            *(float2*)&dst[(size_t)r0 * ld + c] =
                make_float2(acc[mi][ni][0], acc[mi][ni][1]);
            *(float2*)&dst[(size_t)(r0 + 8) * ld + c] =
                make_float2(acc[mi][ni][2], acc[mi][ni][3]);
        }
    }
}

// ---------------- RoPE ----------------------------------------------------
__global__ __launch_bounds__(256) void rope_kernel(
    float* __restrict__ q, float* __restrict__ k)
{
    const int t = blockIdx.x;
    const int idx = blockIdx.y * 256 + threadIdx.x;
    const int head = idx >> 6;
    const int d = idx & 63;

    const float invf = exp2f((float)d * (-13.287712379549449f / 64.0f));
    float fr = (float)t * invf;
    float c = cosf(fr), s = sinf(fr);

    float* base;
    if (head < 16) base = q + ((size_t)t * 16 + head) * 128;
    else           base = k + ((size_t)t * 4 + (head - 16)) * 128;

    float x1 = base[d];
    float x2 = base[d + 64];
    base[d]      = x1 * c - x2 * s;
    base[d + 64] = x1 * s + x2 * c;
}

// =============== tensor-core flash attention (unchanged, R6) ==============
#define KSTR 132
#define PSTR 36

__global__ __launch_bounds__(256) void attn_mma(
    const float* __restrict__ q, const float* __restrict__ k,
    const float* __restrict__ v, float* __restrict__ out)
{
    __shared__ uint32_t KP[4608];
    __shared__ uint32_t Vs[32 * KSTR];

    const int t0   = blockIdx.x * 32;
    const int gh   = blockIdx.y;
    const int tid  = threadIdx.x;
    const int warp = tid >> 5;
    const int lane = tid & 31;
    const int g    = lane >> 2;
    const int tig  = lane & 3;
    const float scale = 0.08838834764831845f;

    const int mA = warp * 16 + g;
    const int mB = mA + 8;
    const int tA = t0 + (mA & 31), tB = t0 + (mB & 31);
    const int hA = gh * 4 + (mA >> 5), hB = gh * 4 + (mB >> 5);

    uint32_t qa[16][4];
    const float* qAp = q + ((size_t)tA * 16 + hA) * 128;
    const float* qBp = q + ((size_t)tB * 16 + hB) * 128;
#pragma unroll
    for (int ks = 0; ks < 16; ks++) {
        qa[ks][0] = f2tf(qAp[8 * ks + tig]);
        qa[ks][1] = f2tf(qBp[8 * ks + tig]);
        qa[ks][2] = f2tf(qAp[8 * ks + tig + 4]);
        qa[ks][3] = f2tf(qBp[8 * ks + tig + 4]);
    }

    float oa[16][4];
#pragma unroll
    for (int i = 0; i < 16; i++)
#pragma unroll
        for (int r = 0; r < 4; r++) oa[i][r] = 0.0f;
    float rmA = -1e30f, rmB = -1e30f, rlA = 0.0f, rlB = 0.0f;

    uint32_t* Pw = &KP[warp * 16 * PSTR];

    for (int c = 0; c < 17; c++) {
        const int sb = t0 - 512 + 32 * c;
        if (sb + 31 < 0) continue;

#pragma unroll
        for (int i = 0; i < 4; i++) {
            int idx = tid + 256 * i;
            int row = idx >> 5;
            int c4  = (idx & 31) * 4;
            int s = sb + row;
            float4 k4 = make_float4(0.f, 0.f, 0.f, 0.f);
            float4 v4 = make_float4(0.f, 0.f, 0.f, 0.f);
            if (s >= 0) {
                k4 = *(const float4*)&k[((size_t)s * 4 + gh) * 128 + c4];
                v4 = *(const float4*)&v[((size_t)s * 4 + gh) * 128 + c4];
            }
            uint4 kp = make_uint4(f2tf(k4.x), f2tf(k4.y), f2tf(k4.z), f2tf(k4.w));
            uint4 vp = make_uint4(f2tf(v4.x), f2tf(v4.y), f2tf(v4.z), f2tf(v4.w));
            *(uint4*)&KP[row * KSTR + c4] = kp;
            *(uint4*)&Vs[row * KSTR + c4] = vp;
        }
        __syncthreads();

        float sf[4][4];
#pragma unroll
        for (int ni = 0; ni < 4; ni++)
#pragma unroll
            for (int r = 0; r < 4; r++) sf[ni][r] = 0.0f;
#pragma unroll
        for (int ks = 0; ks < 16; ks++) {
            const int kk = ks * 8;
#pragma unroll
            for (int ni = 0; ni < 4; ni++) {
                uint32_t b0 = KP[(ni * 8 + g) * KSTR + kk + tig];
                uint32_t b1 = KP[(ni * 8 + g) * KSTR + kk + tig + 4];
                mma_tf32(sf[ni], qa[ks], b0, b1);
            }
        }
        __syncthreads();

        float cmA = -1e30f, cmB = -1e30f;
#pragma unroll
        for (int ni = 0; ni < 4; ni++) {
#pragma unroll
            for (int jj = 0; jj < 2; jj++) {
                const int s = sb + ni * 8 + tig * 2 + jj;
                bool okA = (s >= 0) && (s <= tA) && (tA - s <= 512);
                bool okB = (s >= 0) && (s <= tB) && (tB - s <= 512);
                sf[ni][jj]     = okA ? sf[ni][jj]     * scale : -1e30f;
                sf[ni][2 + jj] = okB ? sf[ni][2 + jj] * scale : -1e30f;
                cmA = fmaxf(cmA, sf[ni][jj]);
                cmB = fmaxf(cmB, sf[ni][2 + jj]);
            }
        }
        cmA = fmaxf(cmA, __shfl_xor_sync(0xffffffffu, cmA, 1));
        cmA = fmaxf(cmA, __shfl_xor_sync(0xffffffffu, cmA, 2));
        cmB = fmaxf(cmB, __shfl_xor_sync(0xffffffffu, cmB, 1));
        cmB = fmaxf(cmB, __shfl_xor_sync(0xffffffffu, cmB, 2));

        const float nmA = fmaxf(rmA, cmA), nmB = fmaxf(rmB, cmB);
        const float alA = __expf(rmA - nmA), alB = __expf(rmB - nmB);
        rmA = nmA; rmB = nmB;

        float clA = 0.f, clB = 0.f;
#pragma unroll
        for (int ni = 0; ni < 4; ni++) {
            float p0 = __expf(sf[ni][0] - nmA);
            float p1 = __expf(sf[ni][1] - nmA);
            float p2 = __expf(sf[ni][2] - nmB);
            float p3 = __expf(sf[ni][3] - nmB);
            clA += p0 + p1; clB += p2 + p3;
            const int col = ni * 8 + tig * 2;
            Pw[g * PSTR + col]           = f2tf(p0);
            Pw[g * PSTR + col + 1]       = f2tf(p1);
            Pw[(g + 8) * PSTR + col]     = f2tf(p2);
            Pw[(g + 8) * PSTR + col + 1] = f2tf(p3);
        }
        clA += __shfl_xor_sync(0xffffffffu, clA, 1);
        clA += __shfl_xor_sync(0xffffffffu, clA, 2);
        clB += __shfl_xor_sync(0xffffffffu, clB, 1);
        clB += __shfl_xor_sync(0xffffffffu, clB, 2);
        rlA = rlA * alA + clA;
        rlB = rlB * alB + clB;

#pragma unroll
        for (int ni2 = 0; ni2 < 16; ni2++) {
            oa[ni2][0] *= alA; oa[ni2][1] *= alA;
            oa[ni2][2] *= alB; oa[ni2][3] *= alB;
        }
        __syncwarp();

#pragma unroll
        for (int ks = 0; ks < 4; ks++) {
            const int kk = ks * 8;
            uint32_t pa[4];
            pa[0] = Pw[g * PSTR + kk + tig];
            pa[1] = Pw[(g + 8) * PSTR + kk + tig];
            pa[2] = Pw[g * PSTR + kk + tig + 4];
            pa[3] = Pw[(g + 8) * PSTR + kk + tig + 4];
#pragma unroll
            for (int ni2 = 0; ni2 < 16; ni2++) {
                uint32_t b0 = Vs[(kk + tig) * KSTR + ni2 * 8 + g];
                uint32_t b1 = Vs[(kk + tig + 4) * KSTR + ni2 * 8 + g];
                mma_tf32(oa[ni2], pa, b0, b1);
            }
        }
        __syncthreads();
    }

    const float ilA = 1.0f / rlA, ilB = 1.0f / rlB;
    float* oAp = out + ((size_t)tA * 16 + hA) * 128;
    float* oBp = out + ((size_t)tB * 16 + hB) * 128;
#pragma unroll
    for (int ni2 = 0; ni2 < 16; ni2++) {
        const int d0 = ni2 * 8 + tig * 2;
        *(float2*)&oAp[d0] = make_float2(oa[ni2][0] * ilA, oa[ni2][1] * ilA);
        *(float2*)&oBp[d0] = make_float2(oa[ni2][2] * ilB, oa[ni2][3] * ilB);
    }
}

// ---------------- launcher -------------------------------------------------
extern "C" void kernel_launch(void* const* d_in, const int* in_sizes, int n_in,
                              void* d_out, int out_size)
{
    const float* x  = (const float*)d_in[0];
    const float* wq = (const float*)d_in[1];
    const float* wk = (const float*)d_in[2];
    const float* wv = (const float*)d_in[3];
    const float* wo = (const float*)d_in[4];
    float* out = (float*)d_out;

    float *q, *k, *v, *att, *wcat;
    cudaGetSymbolAddress((void**)&q,    g_q);
    cudaGetSymbolAddress((void**)&k,    g_k);
    cudaGetSymbolAddress((void**)&v,    g_v);
    cudaGetSymbolAddress((void**)&att,  g_att);
    cudaGetSymbolAddress((void**)&wcat, g_wcat);

    cudaFuncSetAttribute(gemm_db, cudaFuncAttributeMaxDynamicSharedMemorySize,
                         GEMM_SMEM);

    // concatenate [wq; wk; wv] (D2D, graph-capturable)
    cudaMemcpyAsync(wcat,                wq, (size_t)2048 * 2048 * 4,
                    cudaMemcpyDeviceToDevice);
    cudaMemcpyAsync(wcat + 2048 * 2048,  wk, (size_t)512 * 2048 * 4,
                    cudaMemcpyDeviceToDevice);
    cudaMemcpyAsync(wcat + 2560 * 2048,  wv, (size_t)512 * 2048 * 4,
                    cudaMemcpyDeviceToDevice);

    // fused QKV projection
    gemm_db<<<dim3(24, 32), 256, GEMM_SMEM>>>(x, wcat,
                                              q, 2048, 2048,
                                              k, 512, 512,
                                              v, 512, 2048);

    rope_kernel<<<dim3(TLEN, 5), 256>>>(q, k);

    attn_mma<<<dim3(TLEN / 32, 4), 256>>>(q, k, v, att);

    // output projection
    gemm_db<<<dim3(16, 32), 256, GEMM_SMEM>>>(att, wo,
                                              out, 2048, 2048,
                                              out, 0, 2048,
                                              out, 2048, 2048);
}